// round 1
// baseline (speedup 1.0000x reference)
#include <cuda_runtime.h>
#include <math.h>

// Scratch: per-roi packed (flag | argmax<<2). flag: 0=none, 1=pos, 2=neg.
#define GMAX 256
#define BMAX 8
#define RSTRIDE 20480
__device__ unsigned short g_info[BMAX * RSTRIDE];

// ---------------------------------------------------------------------------
// Kernel A: per-roi max IoU + argmax over G gt boxes, classify pos/neg.
// All IoU arithmetic via _rn intrinsics to match JAX fp32 bit-for-bit
// (classification thresholds and argmax ties are bit-sensitive).
// ---------------------------------------------------------------------------
__global__ void classify_kernel(const float4* __restrict__ rois,
                                const float4* __restrict__ gts_raw,
                                int R, int G) {
    int b = blockIdx.y;
    int tid = threadIdx.x;
    __shared__ float4 sgt[GMAX];
    __shared__ float  sarea[GMAX];
    __shared__ int    svalid[GMAX];

    if (tid < G) {
        float4 t = gts_raw[b * G + tid];
        int valid = (t.x != 0.f) || (t.y != 0.f) || (t.z != 0.f) || (t.w != 0.f);
        const float s = 0.0009765625f;  // 1/1024, exact
        t.x *= s; t.y *= s; t.z *= s; t.w *= s;
        sgt[tid] = t;
        sarea[tid] = __fmul_rn(fmaxf(__fsub_rn(t.z, t.x), 0.f),
                               fmaxf(__fsub_rn(t.w, t.y), 0.f));
        svalid[tid] = valid;
    }
    __syncthreads();

    int i = blockIdx.x * blockDim.x + tid;
    if (i >= R) return;

    float4 r = rois[b * R + i];
    bool rvalid = (r.x != 0.f) || (r.y != 0.f) || (r.z != 0.f) || (r.w != 0.f);
    float ar = __fmul_rn(fmaxf(__fsub_rn(r.z, r.x), 0.f),
                         fmaxf(__fsub_rn(r.w, r.y), 0.f));

    float best = -2.0f;   // all iou values are >= -1, first iter always sets
    int bi = 0;

    #pragma unroll 4
    for (int g = 0; g < G; g++) {
        float4 t = sgt[g];
        float ih = fmaxf(__fsub_rn(fminf(r.z, t.z), fmaxf(r.x, t.x)), 0.f);
        float iw = fmaxf(__fsub_rn(fminf(r.w, t.w), fmaxf(r.y, t.y)), 0.f);
        float inter = __fmul_rn(ih, iw);
        float iou;
        if (!svalid[g]) {
            iou = -1.0f;
        } else if (inter == 0.f) {
            iou = 0.0f;           // 0/max(u,eps) == +0 exactly
        } else {
            float uni = fmaxf(__fsub_rn(__fadd_rn(ar, sarea[g]), inter), 1e-7f);
            iou = __fdiv_rn(inter, uni);   // IEEE RN division, same as jnp
        }
        if (iou > best) { best = iou; bi = g; }   // strict >: first-max, matches argmax
    }

    int flag = 0;
    if (rvalid) {
        if (best >= 0.5f)      flag = 1;
        else if (best >= 0.1f) flag = 2;
    }
    g_info[b * RSTRIDE + i] = (unsigned short)(flag | (bi << 2));
}

// ---------------------------------------------------------------------------
// Kernel B: one block per image. Ordered compaction of first 16 positives and
// first 64 negatives (lowest roi index first, matching top_k(R - i)), plus
// total counts; then 64 threads emit s_roi / s_off / s_lab.
// ---------------------------------------------------------------------------
__global__ void select_kernel(const float4* __restrict__ rois,
                              const float4* __restrict__ gts_raw,
                              const int* __restrict__ labels,
                              float* __restrict__ out,
                              int R, int G, int B) {
    int b = blockIdx.x;
    int tid = threadIdx.x;
    int wid = tid >> 5, lane = tid & 31;

    __shared__ int posList[16];
    __shared__ int negList[64];
    __shared__ int wcP[8], wcN[8];
    __shared__ int posTot, negTot;

    if (tid == 0) { posTot = 0; negTot = 0; }
    __syncthreads();

    for (int base = 0; base < R; base += 256) {
        int i = base + tid;
        int fl = (i < R) ? (g_info[b * RSTRIDE + i] & 3) : 0;
        bool isP = (fl == 1), isN = (fl == 2);
        unsigned mP = __ballot_sync(0xffffffffu, isP);
        unsigned mN = __ballot_sync(0xffffffffu, isN);
        if (lane == 0) { wcP[wid] = __popc(mP); wcN[wid] = __popc(mN); }
        __syncthreads();

        int pP = 0, pN = 0, tP = 0, tN = 0;
        #pragma unroll
        for (int w = 0; w < 8; w++) {
            int cp = wcP[w], cn = wcN[w];
            if (w < wid) { pP += cp; pN += cn; }
            tP += cp; tN += cn;
        }
        unsigned ltmask = (1u << lane) - 1u;
        if (isP) {
            int rank = posTot + pP + __popc(mP & ltmask);
            if (rank < 16) posList[rank] = i;
        }
        if (isN) {
            int rank = negTot + pN + __popc(mN & ltmask);
            if (rank < 64) negList[rank] = i;
        }
        __syncthreads();
        if (tid == 0) { posTot += tP; negTot += tN; }
        __syncthreads();
    }

    int n_pos = min(posTot, 16);
    int n_neg = min(negTot, 64 - n_pos);

    if (tid < 64) {
        bool isPos = tid < n_pos;
        bool isNeg = (tid >= n_pos) && (tid < n_pos + n_neg);
        bool valid = isPos || isNeg;
        int ridx = isPos ? posList[tid] : (isNeg ? negList[tid - n_pos] : 0);

        unsigned short info = g_info[b * RSTRIDE + ridx];
        int gidx = info >> 2;

        float roi_o[4] = {0.f, 0.f, 0.f, 0.f};
        float off_o[4] = {0.f, 0.f, 0.f, 0.f};
        int lab = 0;

        if (valid) {
            float4 r = rois[b * R + ridx];
            float4 t = gts_raw[b * G + gidx];
            const float s = 0.0009765625f;
            t.x *= s; t.y *= s; t.z *= s; t.w *= s;

            roi_o[0] = r.x; roi_o[1] = r.y; roi_o[2] = r.z; roi_o[3] = r.w;

            float rh  = fmaxf(r.z - r.x, 1e-7f);
            float rw  = fmaxf(r.w - r.y, 1e-7f);
            float rcy = r.x + 0.5f * rh;
            float rcx = r.y + 0.5f * rw;
            float gh  = fmaxf(t.z - t.x, 1e-7f);
            float gw  = fmaxf(t.w - t.y, 1e-7f);
            float gcy = t.x + 0.5f * gh;
            float gcx = t.y + 0.5f * gw;

            off_o[0] = ((gcy - rcy) / rh) / 0.1f;
            off_o[1] = ((gcx - rcx) / rw) / 0.1f;
            off_o[2] = logf(gh / rh) / 0.2f;
            off_o[3] = logf(gw / rw) / 0.2f;

            if (isPos) lab = labels[b * G + gidx];
        }

        int slotBase = (b * 64 + tid) * 4;
        float* outOff = out + (size_t)B * 64 * 4;
        float* outLab = out + (size_t)2 * B * 64 * 4;
        #pragma unroll
        for (int k = 0; k < 4; k++) {
            out[slotBase + k]    = roi_o[k];
            outOff[slotBase + k] = off_o[k];
        }
        outLab[b * 64 + tid] = (float)lab;
    }
}

extern "C" void kernel_launch(void* const* d_in, const int* in_sizes, int n_in,
                              void* d_out, int out_size) {
    const float4* rois   = (const float4*)d_in[0];   // (B,R,4) f32
    const float4* gts    = (const float4*)d_in[1];   // (B,G,4) f32 (raw pixels)
    const int*    labels = (const int*)d_in[2];      // (B,G) i32
    float* out = (float*)d_out;

    const int G = 256;
    int B = in_sizes[2] / G;
    int R = in_sizes[0] / (4 * B);

    dim3 gridA((R + 255) / 256, B);
    classify_kernel<<<gridA, 256>>>(rois, gts, R, G);
    select_kernel<<<B, 256>>>(rois, gts, labels, out, R, G, B);
}

// round 2
// speedup vs baseline: 1.4112x; 1.4112x over previous
#include <cuda_runtime.h>
#include <math.h>

// flag: 0=none, 1=pos, 2=neg ; packed flag | (argmax_gt << 2)
#define GMAX 256
#define BMAX 8
#define RSTRIDE 20480
#define CHUNK 512
#define MAXCH (RSTRIDE / CHUNK)   // 40

__device__ unsigned short g_info[BMAX * RSTRIDE];
__device__ int2           g_cnt[BMAX * MAXCH];

// ---------------------------------------------------------------------------
// Kernel A: 2 rois/thread. Max-IoU + argmax over G gts, classify, and emit
// per-chunk pos/neg counts. All IoU math via _rn intrinsics (bit-match JAX).
// Invalid gts are rewritten as +inf boxes -> iou == 0 exactly, which never
// changes classification (thresholds are 0.1/0.5) nor argmax of selected rois.
// ---------------------------------------------------------------------------
__global__ void classify_kernel(const float4* __restrict__ rois,
                                const float4* __restrict__ gts_raw,
                                int R, int G, int nChunks) {
    const int b = blockIdx.y;
    const int tid = threadIdx.x;
    __shared__ float4 sgt[GMAX];
    __shared__ float  sarea[GMAX];
    __shared__ int sCntP, sCntN;

    if (tid == 0) { sCntP = 0; sCntN = 0; }
    if (tid < G) {
        float4 t = gts_raw[b * G + tid];
        bool valid = (t.x != 0.f) || (t.y != 0.f) || (t.z != 0.f) || (t.w != 0.f);
        const float s = 0.0009765625f;   // 1/1024 exact
        t.x *= s; t.y *= s; t.z *= s; t.w *= s;
        float area = __fmul_rn(fmaxf(__fsub_rn(t.z, t.x), 0.f),
                               fmaxf(__fsub_rn(t.w, t.y), 0.f));
        if (!valid) {
            const float inf = __int_as_float(0x7f800000);
            t = make_float4(inf, inf, inf, inf);
            area = 0.f;
        }
        sgt[tid] = t;
        sarea[tid] = area;
    }
    __syncthreads();

    const int base = blockIdx.x * CHUNK;
    const int i0 = base + tid;
    const int i1 = base + 256 + tid;

    float4 r0 = (i0 < R) ? rois[b * R + i0] : make_float4(0.f, 0.f, 0.f, 0.f);
    float4 r1 = (i1 < R) ? rois[b * R + i1] : make_float4(0.f, 0.f, 0.f, 0.f);
    bool rv0 = (r0.x != 0.f) || (r0.y != 0.f) || (r0.z != 0.f) || (r0.w != 0.f);
    bool rv1 = (r1.x != 0.f) || (r1.y != 0.f) || (r1.z != 0.f) || (r1.w != 0.f);
    float a0 = __fmul_rn(fmaxf(__fsub_rn(r0.z, r0.x), 0.f),
                         fmaxf(__fsub_rn(r0.w, r0.y), 0.f));
    float a1 = __fmul_rn(fmaxf(__fsub_rn(r1.z, r1.x), 0.f),
                         fmaxf(__fsub_rn(r1.w, r1.y), 0.f));

    float best0 = -1.0f, best1 = -1.0f;
    int bi0 = 0, bi1 = 0;

    #pragma unroll 2
    for (int g = 0; g < G; g++) {
        float4 t = sgt[g];
        float ag = sarea[g];

        float ih0 = fmaxf(__fsub_rn(fminf(r0.z, t.z), fmaxf(r0.x, t.x)), 0.f);
        float iw0 = fmaxf(__fsub_rn(fminf(r0.w, t.w), fmaxf(r0.y, t.y)), 0.f);
        float in0 = __fmul_rn(ih0, iw0);
        float ih1 = fmaxf(__fsub_rn(fminf(r1.z, t.z), fmaxf(r1.x, t.x)), 0.f);
        float iw1 = fmaxf(__fsub_rn(fminf(r1.w, t.w), fmaxf(r1.y, t.y)), 0.f);
        float in1 = __fmul_rn(ih1, iw1);

        float iou0 = 0.f, iou1 = 0.f;
        if (in0 > 0.f)
            iou0 = __fdiv_rn(in0, fmaxf(__fsub_rn(__fadd_rn(a0, ag), in0), 1e-7f));
        if (in1 > 0.f)
            iou1 = __fdiv_rn(in1, fmaxf(__fsub_rn(__fadd_rn(a1, ag), in1), 1e-7f));

        if (iou0 > best0) { best0 = iou0; bi0 = g; }   // strict >: first-max
        if (iou1 > best1) { best1 = iou1; bi1 = g; }
    }

    int f0 = 0, f1 = 0;
    if (rv0) { if (best0 >= 0.5f) f0 = 1; else if (best0 >= 0.1f) f0 = 2; }
    if (rv1) { if (best1 >= 0.5f) f1 = 1; else if (best1 >= 0.1f) f1 = 2; }

    if (i0 < R) g_info[b * RSTRIDE + i0] = (unsigned short)(f0 | (bi0 << 2));
    if (i1 < R) g_info[b * RSTRIDE + i1] = (unsigned short)(f1 | (bi1 << 2));

    // per-chunk counts
    unsigned p = __popc(__ballot_sync(0xffffffffu, f0 == 1)) +
                 __popc(__ballot_sync(0xffffffffu, f1 == 1));
    unsigned n = __popc(__ballot_sync(0xffffffffu, f0 == 2)) +
                 __popc(__ballot_sync(0xffffffffu, f1 == 2));
    if ((tid & 31) == 0) {
        atomicAdd(&sCntP, (int)p);
        atomicAdd(&sCntN, (int)n);
    }
    __syncthreads();
    if (tid == 0)
        g_cnt[b * MAXCH + blockIdx.x] = make_int2(sCntP, sCntN);
}

// ---------------------------------------------------------------------------
// Kernel B: one block/image. Prefix over chunk counts, then warps scan only
// contributing chunks with globally absolute ballot ranks; 64 threads emit.
// ---------------------------------------------------------------------------
__global__ void select_kernel(const float4* __restrict__ rois,
                              const float4* __restrict__ gts_raw,
                              const int* __restrict__ labels,
                              float* __restrict__ out,
                              int R, int G, int B, int nChunks) {
    const int b = blockIdx.x;
    const int tid = threadIdx.x;
    const int wid = tid >> 5, lane = tid & 31;

    __shared__ int prefP[MAXCH + 1], prefN[MAXCH + 1];
    __shared__ int cp[MAXCH], cn[MAXCH];
    __shared__ int posList[16];
    __shared__ int negList[64];

    if (tid < nChunks) {
        int2 c = g_cnt[b * MAXCH + tid];
        cp[tid] = c.x; cn[tid] = c.y;
    }
    __syncthreads();
    if (tid == 0) {
        int sp = 0, sn = 0;
        for (int c = 0; c < nChunks; c++) {
            prefP[c] = sp; prefN[c] = sn;
            sp += cp[c]; sn += cn[c];
        }
        prefP[nChunks] = sp; prefN[nChunks] = sn;
    }
    __syncthreads();

    const unsigned ltmask = (1u << lane) - 1u;
    for (int c = wid; c < nChunks; c += 8) {
        int pr = prefP[c], nr = prefN[c];
        bool needP = (pr < 16) && (prefP[c + 1] > pr);
        bool needN = (nr < 64) && (prefN[c + 1] > nr);
        if (!needP && !needN) continue;
        for (int s = 0; s < CHUNK; s += 32) {
            int i = c * CHUNK + s + lane;
            int fl = (i < R) ? (g_info[b * RSTRIDE + i] & 3) : 0;
            unsigned mP = __ballot_sync(0xffffffffu, fl == 1);
            unsigned mN = __ballot_sync(0xffffffffu, fl == 2);
            if (fl == 1) {
                int rank = pr + __popc(mP & ltmask);
                if (rank < 16) posList[rank] = i;
            }
            if (fl == 2) {
                int rank = nr + __popc(mN & ltmask);
                if (rank < 64) negList[rank] = i;
            }
            pr += __popc(mP); nr += __popc(mN);
            if (pr >= 16 && nr >= 64) break;   // uniform across warp
        }
    }
    __syncthreads();

    int posTot = prefP[nChunks], negTot = prefN[nChunks];
    int n_pos = min(posTot, 16);
    int n_neg = min(negTot, 64 - n_pos);

    if (tid < 64) {
        bool isPos = tid < n_pos;
        bool isNeg = (tid >= n_pos) && (tid < n_pos + n_neg);
        bool valid = isPos || isNeg;
        int ridx = isPos ? posList[tid] : (isNeg ? negList[tid - n_pos] : 0);

        float roi_o[4] = {0.f, 0.f, 0.f, 0.f};
        float off_o[4] = {0.f, 0.f, 0.f, 0.f};
        int lab = 0;

        if (valid) {
            unsigned short info = g_info[b * RSTRIDE + ridx];
            int gidx = info >> 2;
            float4 r = rois[b * R + ridx];
            float4 t = gts_raw[b * G + gidx];
            const float s = 0.0009765625f;
            t.x *= s; t.y *= s; t.z *= s; t.w *= s;

            roi_o[0] = r.x; roi_o[1] = r.y; roi_o[2] = r.z; roi_o[3] = r.w;

            float rh  = fmaxf(r.z - r.x, 1e-7f);
            float rw  = fmaxf(r.w - r.y, 1e-7f);
            float rcy = r.x + 0.5f * rh;
            float rcx = r.y + 0.5f * rw;
            float gh  = fmaxf(t.z - t.x, 1e-7f);
            float gw  = fmaxf(t.w - t.y, 1e-7f);
            float gcy = t.x + 0.5f * gh;
            float gcx = t.y + 0.5f * gw;

            off_o[0] = ((gcy - rcy) / rh) / 0.1f;
            off_o[1] = ((gcx - rcx) / rw) / 0.1f;
            off_o[2] = logf(gh / rh) / 0.2f;
            off_o[3] = logf(gw / rw) / 0.2f;

            if (isPos) lab = labels[b * G + gidx];
        }

        int slotBase = (b * 64 + tid) * 4;
        float* outOff = out + (size_t)B * 64 * 4;
        float* outLab = out + (size_t)2 * B * 64 * 4;
        #pragma unroll
        for (int k = 0; k < 4; k++) {
            out[slotBase + k]    = roi_o[k];
            outOff[slotBase + k] = off_o[k];
        }
        outLab[b * 64 + tid] = (float)lab;
    }
}

extern "C" void kernel_launch(void* const* d_in, const int* in_sizes, int n_in,
                              void* d_out, int out_size) {
    const float4* rois   = (const float4*)d_in[0];   // (B,R,4) f32
    const float4* gts    = (const float4*)d_in[1];   // (B,G,4) f32 raw pixels
    const int*    labels = (const int*)d_in[2];      // (B,G) i32
    float* out = (float*)d_out;

    const int G = 256;
    int B = in_sizes[2] / G;
    int R = in_sizes[0] / (4 * B);
    int nChunks = (R + CHUNK - 1) / CHUNK;

    dim3 gridA(nChunks, B);
    classify_kernel<<<gridA, 256>>>(rois, gts, R, G, nChunks);
    select_kernel<<<B, 256>>>(rois, gts, labels, out, R, G, B, nChunks);
}

// round 3
// speedup vs baseline: 2.0298x; 1.4384x over previous
#include <cuda_runtime.h>
#include <math.h>

// flag: 0=none, 1=pos, 2=neg ; packed flag | (argmax_gt << 2)
#define GMAX 256
#define BMAX 8
#define RSTRIDE 20480
#define CHUNK 256
#define MAXCH (RSTRIDE / CHUNK)   // 80

__device__ unsigned short g_info[BMAX * RSTRIDE];
__device__ int2           g_cnt[BMAX * MAXCH];

// ---------------------------------------------------------------------------
// Kernel A: 1 roi/thread, 256-roi chunks. Division-free running-max scan;
// exact __fdiv_rn only on rare candidate updates (bit-matches JAX max/argmax
// and thresholds: skip is provably safe with the (1-2^-22) margin).
// Invalid gts rewritten as +inf boxes -> inter==0 -> never pass the gate.
// ---------------------------------------------------------------------------
__global__ void classify_kernel(const float4* __restrict__ rois,
                                const float4* __restrict__ gts_raw,
                                int R, int G) {
    const int b = blockIdx.y;
    const int tid = threadIdx.x;
    const int wid = tid >> 5, lane = tid & 31;
    __shared__ float4 sgt[GMAX];
    __shared__ float  sarea[GMAX];
    __shared__ int    sP[8], sN[8];

    if (tid < G) {
        float4 t = gts_raw[b * G + tid];
        bool valid = (t.x != 0.f) || (t.y != 0.f) || (t.z != 0.f) || (t.w != 0.f);
        const float s = 0.0009765625f;   // 1/1024 exact
        t.x *= s; t.y *= s; t.z *= s; t.w *= s;
        float area = __fmul_rn(fmaxf(__fsub_rn(t.z, t.x), 0.f),
                               fmaxf(__fsub_rn(t.w, t.y), 0.f));
        if (!valid) {
            const float inf = __int_as_float(0x7f800000);
            t = make_float4(inf, inf, inf, inf);
            area = 0.f;
        }
        sgt[tid] = t;
        sarea[tid] = area;
    }
    __syncthreads();

    const int i = blockIdx.x * CHUNK + tid;
    float4 r = (i < R) ? rois[b * R + i] : make_float4(0.f, 0.f, 0.f, 0.f);
    bool rvalid = (r.x != 0.f) || (r.y != 0.f) || (r.z != 0.f) || (r.w != 0.f);
    float ar = __fmul_rn(fmaxf(__fsub_rn(r.z, r.x), 0.f),
                         fmaxf(__fsub_rn(r.w, r.y), 0.f));

    float best = 0.f;        // matches reference: non-overlap iou == 0
    float bestS = 0.f;       // best * (1 - 2^-22), conservative gate
    int bi = 0;

    #pragma unroll 4
    for (int g = 0; g < G; g++) {
        float4 t = sgt[g];
        float ag = sarea[g];

        float ih = fmaxf(__fsub_rn(fminf(r.z, t.z), fmaxf(r.x, t.x)), 0.f);
        float iw = fmaxf(__fsub_rn(fminf(r.w, t.w), fmaxf(r.y, t.y)), 0.f);
        float inter = __fmul_rn(ih, iw);
        float uni = fmaxf(__fsub_rn(__fadd_rn(ar, ag), inter), 1e-7f);

        if (inter > __fmul_rn(bestS, uni)) {      // rare (running-max records)
            float iou = __fdiv_rn(inter, uni);    // exact, same as jnp
            if (iou > best) {                     // strict >: first-max wins
                best = iou;
                bestS = __fmul_rn(iou, 0.99999976158142089844f); // 1 - 2^-22
                bi = g;
            }
        }
    }

    int fl = 0;
    if (rvalid) {
        if (best >= 0.5f)      fl = 1;
        else if (best >= 0.1f) fl = 2;
    }
    if (i < R) g_info[b * RSTRIDE + i] = (unsigned short)(fl | (bi << 2));

    unsigned mP = __ballot_sync(0xffffffffu, fl == 1);
    unsigned mN = __ballot_sync(0xffffffffu, fl == 2);
    if (lane == 0) { sP[wid] = __popc(mP); sN[wid] = __popc(mN); }
    __syncthreads();
    if (tid == 0) {
        int p = 0, n = 0;
        #pragma unroll
        for (int w = 0; w < 8; w++) { p += sP[w]; n += sN[w]; }
        g_cnt[b * MAXCH + blockIdx.x] = make_int2(p, n);
    }
}

// ---------------------------------------------------------------------------
// Kernel B: one block/image. Prefix over chunk counts; warps scan only the
// chunks that can still contribute, with globally absolute ballot ranks.
// ---------------------------------------------------------------------------
__global__ void select_kernel(const float4* __restrict__ rois,
                              const float4* __restrict__ gts_raw,
                              const int* __restrict__ labels,
                              float* __restrict__ out,
                              int R, int G, int B, int nChunks) {
    const int b = blockIdx.x;
    const int tid = threadIdx.x;
    const int wid = tid >> 5, lane = tid & 31;

    __shared__ int prefP[MAXCH + 1], prefN[MAXCH + 1];
    __shared__ int cp[MAXCH], cn[MAXCH];
    __shared__ int posList[16];
    __shared__ int negList[64];

    if (tid < nChunks) {
        int2 c = g_cnt[b * MAXCH + tid];
        cp[tid] = c.x; cn[tid] = c.y;
    }
    __syncthreads();
    if (tid == 0) {
        int sp = 0, sn = 0;
        for (int c = 0; c < nChunks; c++) {
            prefP[c] = sp; prefN[c] = sn;
            sp += cp[c]; sn += cn[c];
        }
        prefP[nChunks] = sp; prefN[nChunks] = sn;
    }
    __syncthreads();

    const unsigned ltmask = (1u << lane) - 1u;
    for (int c = wid; c < nChunks; c += 8) {
        int pr = prefP[c], nr = prefN[c];
        bool needP = (pr < 16) && (prefP[c + 1] > pr);
        bool needN = (nr < 64) && (prefN[c + 1] > nr);
        if (!needP && !needN) continue;
        for (int s = 0; s < CHUNK; s += 32) {
            int i = c * CHUNK + s + lane;
            int fl = (i < R) ? (g_info[b * RSTRIDE + i] & 3) : 0;
            unsigned mP = __ballot_sync(0xffffffffu, fl == 1);
            unsigned mN = __ballot_sync(0xffffffffu, fl == 2);
            if (fl == 1) {
                int rank = pr + __popc(mP & ltmask);
                if (rank < 16) posList[rank] = i;
            }
            if (fl == 2) {
                int rank = nr + __popc(mN & ltmask);
                if (rank < 64) negList[rank] = i;
            }
            pr += __popc(mP); nr += __popc(mN);
            if (pr >= 16 && nr >= 64) break;   // uniform across warp
        }
    }
    __syncthreads();

    int posTot = prefP[nChunks], negTot = prefN[nChunks];
    int n_pos = min(posTot, 16);
    int n_neg = min(negTot, 64 - n_pos);

    if (tid < 64) {
        bool isPos = tid < n_pos;
        bool isNeg = (tid >= n_pos) && (tid < n_pos + n_neg);
        bool valid = isPos || isNeg;
        int ridx = isPos ? posList[tid] : (isNeg ? negList[tid - n_pos] : 0);

        float roi_o[4] = {0.f, 0.f, 0.f, 0.f};
        float off_o[4] = {0.f, 0.f, 0.f, 0.f};
        int lab = 0;

        if (valid) {
            unsigned short info = g_info[b * RSTRIDE + ridx];
            int gidx = info >> 2;
            float4 r = rois[b * R + ridx];
            float4 t = gts_raw[b * G + gidx];
            const float s = 0.0009765625f;
            t.x *= s; t.y *= s; t.z *= s; t.w *= s;

            roi_o[0] = r.x; roi_o[1] = r.y; roi_o[2] = r.z; roi_o[3] = r.w;

            float rh  = fmaxf(r.z - r.x, 1e-7f);
            float rw  = fmaxf(r.w - r.y, 1e-7f);
            float rcy = r.x + 0.5f * rh;
            float rcx = r.y + 0.5f * rw;
            float gh  = fmaxf(t.z - t.x, 1e-7f);
            float gw  = fmaxf(t.w - t.y, 1e-7f);
            float gcy = t.x + 0.5f * gh;
            float gcx = t.y + 0.5f * gw;

            off_o[0] = ((gcy - rcy) / rh) / 0.1f;
            off_o[1] = ((gcx - rcx) / rw) / 0.1f;
            off_o[2] = logf(gh / rh) / 0.2f;
            off_o[3] = logf(gw / rw) / 0.2f;

            if (isPos) lab = labels[b * G + gidx];
        }

        int slotBase = (b * 64 + tid) * 4;
        float* outOff = out + (size_t)B * 64 * 4;
        float* outLab = out + (size_t)2 * B * 64 * 4;
        #pragma unroll
        for (int k = 0; k < 4; k++) {
            out[slotBase + k]    = roi_o[k];
            outOff[slotBase + k] = off_o[k];
        }
        outLab[b * 64 + tid] = (float)lab;
    }
}

extern "C" void kernel_launch(void* const* d_in, const int* in_sizes, int n_in,
                              void* d_out, int out_size) {
    const float4* rois   = (const float4*)d_in[0];   // (B,R,4) f32
    const float4* gts    = (const float4*)d_in[1];   // (B,G,4) f32 raw pixels
    const int*    labels = (const int*)d_in[2];      // (B,G) i32
    float* out = (float*)d_out;

    const int G = 256;
    int B = in_sizes[2] / G;
    int R = in_sizes[0] / (4 * B);
    int nChunks = (R + CHUNK - 1) / CHUNK;

    dim3 gridA(nChunks, B);
    classify_kernel<<<gridA, 256>>>(rois, gts, R, G);
    select_kernel<<<B, 256>>>(rois, gts, labels, out, R, G, B, nChunks);
}

// round 4
// speedup vs baseline: 2.1102x; 1.0396x over previous
#include <cuda_runtime.h>
#include <math.h>

// flag: 0=none, 1=pos, 2=neg ; packed flag | (argmax_gt << 2)
#define GMAX 256
#define BMAX 8
#define RSTRIDE 20480
#define CHUNK 256
#define MAXCH (RSTRIDE / CHUNK)   // 80
#define FULLM 0xffffffffu

__device__ unsigned short g_info[BMAX * RSTRIDE];
__device__ int2           g_cnt[BMAX * MAXCH];
__device__ int            g_done = 0;

// ---------------------------------------------------------------------------
// Fused kernel. Phase 1 (all blocks): per-roi max-IoU/argmax with a division-
// free FMA gate; exact __fdiv_rn only on rare candidates so best/argmax and
// the 0.5/0.1 thresholds bit-match JAX. Phase 2 (last finishing block only):
// warp-per-image deterministic subsample + output emit.
// ---------------------------------------------------------------------------
__global__ void fused_kernel(const float4* __restrict__ rois,
                             const float4* __restrict__ gts_raw,
                             const int* __restrict__ labels,
                             float* __restrict__ out,
                             int R, int G, int B, int nChunks, int totalBlocks) {
    const int b = blockIdx.y;
    const int tid = threadIdx.x;
    const int wid = tid >> 5, lane = tid & 31;

    __shared__ float4 sgt[GMAX];
    __shared__ float  sarea[GMAX];
    __shared__ int    sP[8], sN[8];
    __shared__ int    sTicket;
    __shared__ int    posList[BMAX][16];
    __shared__ int    negList[BMAX][64];

    // ---- stage gts ----
    if (tid < G) {
        float4 t = gts_raw[b * G + tid];
        bool valid = (t.x != 0.f) || (t.y != 0.f) || (t.z != 0.f) || (t.w != 0.f);
        const float s = 0.0009765625f;   // 1/1024 exact
        t.x *= s; t.y *= s; t.z *= s; t.w *= s;
        float area = __fmul_rn(fmaxf(__fsub_rn(t.z, t.x), 0.f),
                               fmaxf(__fsub_rn(t.w, t.y), 0.f));
        if (!valid) {
            const float inf = __int_as_float(0x7f800000);
            t = make_float4(inf, inf, inf, inf);  // ih = -inf -> gate fails
            area = 0.f;
        }
        sgt[tid] = t;
        sarea[tid] = area;
    }
    __syncthreads();

    // ---- phase 1: classify ----
    const int i = blockIdx.x * CHUNK + tid;
    float4 r = (i < R) ? rois[b * R + i] : make_float4(0.f, 0.f, 0.f, 0.f);
    bool rvalid = (r.x != 0.f) || (r.y != 0.f) || (r.z != 0.f) || (r.w != 0.f);
    float ar = __fmul_rn(fmaxf(__fsub_rn(r.z, r.x), 0.f),
                         fmaxf(__fsub_rn(r.w, r.y), 0.f));

    float best = 0.f;      // matches reference: non-overlap iou == 0
    float cGate = 0.f;     // ~ best/(1+best), conservatively shrunk
    float car = 0.f;       // cGate * ar
    int bi = 0;

    #pragma unroll 4
    for (int g = 0; g < G; g++) {
        float4 t = sgt[g];
        float ag = sarea[g];

        float ih = __fsub_rn(fminf(r.z, t.z), fmaxf(r.x, t.x));
        float iw = __fsub_rn(fminf(r.w, t.w), fmaxf(r.y, t.y));
        float prod = __fmul_rn(ih, iw);
        float thresh = __fmaf_rn(cGate, ag, car);   // ~ cGate*(ar+ag), >= 0

        if (prod > thresh && ih > 0.f) {            // rare: candidate update
            // here ih>0 and (prod>thresh>=0) => iw>0, so clamps are no-ops
            float uni = fmaxf(__fsub_rn(__fadd_rn(ar, ag), prod), 1e-7f);
            float iou = __fdiv_rn(prod, uni);       // exact, same as jnp
            if (iou > best) {                       // strict >: first-max wins
                best = iou; bi = g;
                float bb = __fmul_rn(iou, 0.999969482421875f);     // 1-2^-15
                float cg = __fmul_rn(__fdiv_rn(bb, __fadd_rn(1.0f, bb)),
                                     0.999969482421875f);          // shrink again
                cGate = cg;
                car = __fmul_rn(cg, ar);
            }
        }
    }

    int fl = 0;
    if (rvalid) {
        if (best >= 0.5f)      fl = 1;
        else if (best >= 0.1f) fl = 2;
    }
    if (i < R) g_info[b * RSTRIDE + i] = (unsigned short)(fl | (bi << 2));

    unsigned mP = __ballot_sync(FULLM, fl == 1);
    unsigned mN = __ballot_sync(FULLM, fl == 2);
    if (lane == 0) { sP[wid] = __popc(mP); sN[wid] = __popc(mN); }
    __syncthreads();
    if (tid == 0) {
        int p = 0, n = 0;
        #pragma unroll
        for (int w = 0; w < 8; w++) { p += sP[w]; n += sN[w]; }
        g_cnt[b * MAXCH + blockIdx.x] = make_int2(p, n);
    }

    // ---- last-block ticket ----
    __threadfence();
    __syncthreads();
    if (tid == 0) sTicket = atomicAdd(&g_done, 1);
    __syncthreads();
    if (sTicket != totalBlocks - 1) return;
    if (tid == 0) g_done = 0;     // reset for next graph replay
    __threadfence();              // acquire: all blocks' g_info/g_cnt visible

    // ---- phase 2: warp per image ----
    for (int img = wid; img < B; img += 8) {
        const int imgOff = img * RSTRIDE;

        int carryP = 0, carryN = 0;
        for (int base = 0; base < nChunks; base += 32) {
            if (carryP >= 16 && carryN >= 64) break;
            int c = base + lane;
            int2 cc = (c < nChunks) ? g_cnt[img * MAXCH + c] : make_int2(0, 0);
            int sp = cc.x, sn = cc.y;
            #pragma unroll
            for (int o = 1; o < 32; o <<= 1) {
                int tp = __shfl_up_sync(FULLM, sp, o);
                int tn = __shfl_up_sync(FULLM, sn, o);
                if (lane >= o) { sp += tp; sn += tn; }
            }
            int exP = carryP + sp - cc.x;   // exclusive prefix of chunk c
            int exN = carryN + sn - cc.y;
            bool need = (c < nChunks) &&
                        (((exP < 16) && (cc.x > 0)) || ((exN < 64) && (cc.y > 0)));
            unsigned needMask = __ballot_sync(FULLM, need);
            int totP = __shfl_sync(FULLM, sp, 31);
            int totN = __shfl_sync(FULLM, sn, 31);

            while (needMask) {
                int cl = __ffs(needMask) - 1;
                needMask &= needMask - 1;
                int cidx = base + cl;
                int pr = __shfl_sync(FULLM, exP, cl);
                int nr = __shfl_sync(FULLM, exN, cl);
                int cbase = cidx * CHUNK;
                int flv[8];
                #pragma unroll
                for (int k = 0; k < 8; k++) {
                    int idx = cbase + k * 32 + lane;
                    flv[k] = (idx < R) ? (g_info[imgOff + idx] & 3) : 0;
                }
                const unsigned ltm = (1u << lane) - 1u;
                #pragma unroll
                for (int k = 0; k < 8; k++) {
                    unsigned bP = __ballot_sync(FULLM, flv[k] == 1);
                    unsigned bN = __ballot_sync(FULLM, flv[k] == 2);
                    if (flv[k] == 1) {
                        int rank = pr + __popc(bP & ltm);
                        if (rank < 16) posList[img][rank] = cbase + k * 32 + lane;
                    }
                    if (flv[k] == 2) {
                        int rank = nr + __popc(bN & ltm);
                        if (rank < 64) negList[img][rank] = cbase + k * 32 + lane;
                    }
                    pr += __popc(bP); nr += __popc(bN);
                }
            }
            carryP += totP; carryN += totN;
        }
        __syncwarp();

        int n_pos = min(carryP, 16);
        int n_neg = min(carryN, 64 - n_pos);

        for (int slot = lane; slot < 64; slot += 32) {
            bool isPos = slot < n_pos;
            bool isNeg = (slot >= n_pos) && (slot < n_pos + n_neg);
            bool valid = isPos || isNeg;
            int ridx = isPos ? posList[img][slot]
                             : (isNeg ? negList[img][slot - n_pos] : 0);

            float roi_o[4] = {0.f, 0.f, 0.f, 0.f};
            float off_o[4] = {0.f, 0.f, 0.f, 0.f};
            int lab = 0;

            if (valid) {
                unsigned short info = g_info[imgOff + ridx];
                int gidx = info >> 2;
                float4 rr = rois[img * R + ridx];
                float4 tt = gts_raw[img * G + gidx];
                const float s = 0.0009765625f;
                tt.x *= s; tt.y *= s; tt.z *= s; tt.w *= s;

                roi_o[0] = rr.x; roi_o[1] = rr.y; roi_o[2] = rr.z; roi_o[3] = rr.w;

                float rh  = fmaxf(rr.z - rr.x, 1e-7f);
                float rw  = fmaxf(rr.w - rr.y, 1e-7f);
                float rcy = rr.x + 0.5f * rh;
                float rcx = rr.y + 0.5f * rw;
                float gh  = fmaxf(tt.z - tt.x, 1e-7f);
                float gw  = fmaxf(tt.w - tt.y, 1e-7f);
                float gcy = tt.x + 0.5f * gh;
                float gcx = tt.y + 0.5f * gw;

                off_o[0] = ((gcy - rcy) / rh) / 0.1f;
                off_o[1] = ((gcx - rcx) / rw) / 0.1f;
                off_o[2] = logf(gh / rh) / 0.2f;
                off_o[3] = logf(gw / rw) / 0.2f;

                if (isPos) lab = labels[img * G + gidx];
            }

            int slotBase = (img * 64 + slot) * 4;
            float* outOff = out + (size_t)B * 64 * 4;
            float* outLab = out + (size_t)2 * B * 64 * 4;
            #pragma unroll
            for (int k = 0; k < 4; k++) {
                out[slotBase + k]    = roi_o[k];
                outOff[slotBase + k] = off_o[k];
            }
            outLab[img * 64 + slot] = (float)lab;
        }
    }
}

extern "C" void kernel_launch(void* const* d_in, const int* in_sizes, int n_in,
                              void* d_out, int out_size) {
    const float4* rois   = (const float4*)d_in[0];   // (B,R,4) f32
    const float4* gts    = (const float4*)d_in[1];   // (B,G,4) f32 raw pixels
    const int*    labels = (const int*)d_in[2];      // (B,G) i32
    float* out = (float*)d_out;

    const int G = 256;
    int B = in_sizes[2] / G;
    int R = in_sizes[0] / (4 * B);
    int nChunks = (R + CHUNK - 1) / CHUNK;

    dim3 grid(nChunks, B);
    fused_kernel<<<grid, 256>>>(rois, gts, labels, out, R, G, B, nChunks,
                                nChunks * B);
}

// round 5
// speedup vs baseline: 2.7484x; 1.3024x over previous
#include <cuda_runtime.h>
#include <math.h>

// flag: 0=none, 1=pos, 2=neg ; packed flag | (argmax_gt << 2)
#define GMAX 256
#define BMAX 8
#define RSTRIDE 20480
#define CHUNK 256
#define MAXCH (RSTRIDE / CHUNK)   // 80
#define FULLM 0xffffffffu

__device__ unsigned short g_info[BMAX * RSTRIDE];
__device__ int2           g_cnt[BMAX * MAXCH];
__device__ int            g_done = 0;

// ---------------------------------------------------------------------------
// Fused kernel. Phase 1: branchless division-free max-IoU tournament.
// Ordering by prod/s (s = ar+ag) == ordering by prod/(s-prod) = IoU exactly;
// cross-multiplied comparison avoids all division in the loop. One exact
// __fdiv_rn per roi at the end reproduces JAX's rounded quotient bit-exactly.
// Phase 2 (last finishing block): warp-per-image subsample + emit.
// ---------------------------------------------------------------------------
__global__ void fused_kernel(const float4* __restrict__ rois,
                             const float4* __restrict__ gts_raw,
                             const int* __restrict__ labels,
                             float* __restrict__ out,
                             int R, int G, int B, int nChunks, int totalBlocks) {
    const int b = blockIdx.y;
    const int tid = threadIdx.x;
    const int wid = tid >> 5, lane = tid & 31;

    __shared__ float4 sgt[GMAX];     // (tz, tw, tx, ty)
    __shared__ float  sarea[GMAX];
    __shared__ int    sP[8], sN[8];
    __shared__ int    sTicket;
    __shared__ int    posList[BMAX][16];
    __shared__ int    negList[BMAX][64];

    // ---- stage gts ----
    if (tid < G) {
        float4 t = gts_raw[b * G + tid];
        bool valid = (t.x != 0.f) || (t.y != 0.f) || (t.z != 0.f) || (t.w != 0.f);
        const float s = 0.0009765625f;   // 1/1024 exact
        t.x *= s; t.y *= s; t.z *= s; t.w *= s;
        float area = __fmul_rn(fmaxf(__fsub_rn(t.z, t.x), 0.f),
                               fmaxf(__fsub_rn(t.w, t.y), 0.f));
        if (!valid) {
            const float inf = __int_as_float(0x7f800000);
            t = make_float4(inf, inf, inf, inf);  // prod -> NaN/neg, never updates
            area = 0.f;
        }
        sgt[tid] = make_float4(t.z, t.w, t.x, t.y);  // (tz,tw,tx,ty)
        sarea[tid] = area;
    }
    __syncthreads();

    // ---- phase 1: classify (branchless) ----
    const int i = blockIdx.x * CHUNK + tid;
    float4 r = (i < R) ? rois[b * R + i] : make_float4(0.f, 0.f, 0.f, 0.f);
    bool rvalid = (r.x != 0.f) || (r.y != 0.f) || (r.z != 0.f) || (r.w != 0.f);
    float ar = __fmul_rn(fmaxf(__fsub_rn(r.z, r.x), 0.f),
                         fmaxf(__fsub_rn(r.w, r.y), 0.f));
    const float rx = r.x, ry = r.y, rz = r.z, rw = r.w;

    float bestP = 0.f;   // committed inter (ref-exact on commit)
    float bestS = 1.f;   // committed fl(ar+ag)
    int bi = 0;

    #pragma unroll 8
    for (int g = 0; g < G; g++) {
        float4 t = sgt[g];            // t.x=tz t.y=tw t.z=tx t.w=ty
        float ag = sarea[g];

        float minz = fminf(rz, t.x);
        float minw = fminf(rw, t.y);
        float maxx = fmaxf(rx, t.z);
        float maxy = fmaxf(ry, t.w);
        float ih = fmaxf(__fsub_rn(minz, maxx), 0.f);
        float iw = __fsub_rn(minw, maxy);
        float prod = __fmul_rn(ih, iw);       // == ref inter when it can win
        float s    = __fadd_rn(ar, ag);

        // prod/s ordering == IoU ordering; cross-mult, strict > keeps first-max
        bool upd = __fmul_rn(prod, bestS) > __fmul_rn(bestP, s);
        bestP = upd ? prod : bestP;
        bestS = upd ? s    : bestS;
        bi    = upd ? g    : bi;
    }

    float uni  = fmaxf(__fsub_rn(bestS, bestP), 1e-7f);
    float best = __fdiv_rn(bestP, uni);       // exact ref rounding

    int fl = 0;
    if (rvalid) {
        if (best >= 0.5f)      fl = 1;
        else if (best >= 0.1f) fl = 2;
    }
    if (i < R) g_info[b * RSTRIDE + i] = (unsigned short)(fl | (bi << 2));

    unsigned mP = __ballot_sync(FULLM, fl == 1);
    unsigned mN = __ballot_sync(FULLM, fl == 2);
    if (lane == 0) { sP[wid] = __popc(mP); sN[wid] = __popc(mN); }
    __syncthreads();
    if (tid == 0) {
        int p = 0, n = 0;
        #pragma unroll
        for (int w = 0; w < 8; w++) { p += sP[w]; n += sN[w]; }
        g_cnt[b * MAXCH + blockIdx.x] = make_int2(p, n);
    }

    // ---- last-block ticket ----
    __threadfence();
    __syncthreads();
    if (tid == 0) sTicket = atomicAdd(&g_done, 1);
    __syncthreads();
    if (sTicket != totalBlocks - 1) return;
    if (tid == 0) g_done = 0;     // reset for next graph replay
    __threadfence();              // acquire: all blocks' g_info/g_cnt visible

    // ---- phase 2: warp per image ----
    for (int img = wid; img < B; img += 8) {
        const int imgOff = img * RSTRIDE;

        int carryP = 0, carryN = 0;
        for (int base = 0; base < nChunks; base += 32) {
            if (carryP >= 16 && carryN >= 64) break;
            int c = base + lane;
            int2 cc = (c < nChunks) ? g_cnt[img * MAXCH + c] : make_int2(0, 0);
            int sp = cc.x, sn = cc.y;
            #pragma unroll
            for (int o = 1; o < 32; o <<= 1) {
                int tp = __shfl_up_sync(FULLM, sp, o);
                int tn = __shfl_up_sync(FULLM, sn, o);
                if (lane >= o) { sp += tp; sn += tn; }
            }
            int exP = carryP + sp - cc.x;   // exclusive prefix of chunk c
            int exN = carryN + sn - cc.y;
            bool need = (c < nChunks) &&
                        (((exP < 16) && (cc.x > 0)) || ((exN < 64) && (cc.y > 0)));
            unsigned needMask = __ballot_sync(FULLM, need);
            int totP = __shfl_sync(FULLM, sp, 31);
            int totN = __shfl_sync(FULLM, sn, 31);

            while (needMask) {
                int cl = __ffs(needMask) - 1;
                needMask &= needMask - 1;
                int cidx = base + cl;
                int pr = __shfl_sync(FULLM, exP, cl);
                int nr = __shfl_sync(FULLM, exN, cl);
                int cbase = cidx * CHUNK;
                int flv[8];
                #pragma unroll
                for (int k = 0; k < 8; k++) {
                    int idx = cbase + k * 32 + lane;
                    flv[k] = (idx < R) ? (g_info[imgOff + idx] & 3) : 0;
                }
                const unsigned ltm = (1u << lane) - 1u;
                #pragma unroll
                for (int k = 0; k < 8; k++) {
                    unsigned bP = __ballot_sync(FULLM, flv[k] == 1);
                    unsigned bN = __ballot_sync(FULLM, flv[k] == 2);
                    if (flv[k] == 1) {
                        int rank = pr + __popc(bP & ltm);
                        if (rank < 16) posList[img][rank] = cbase + k * 32 + lane;
                    }
                    if (flv[k] == 2) {
                        int rank = nr + __popc(bN & ltm);
                        if (rank < 64) negList[img][rank] = cbase + k * 32 + lane;
                    }
                    pr += __popc(bP); nr += __popc(bN);
                }
            }
            carryP += totP; carryN += totN;
        }
        __syncwarp();

        int n_pos = min(carryP, 16);
        int n_neg = min(carryN, 64 - n_pos);

        for (int slot = lane; slot < 64; slot += 32) {
            bool isPos = slot < n_pos;
            bool isNeg = (slot >= n_pos) && (slot < n_pos + n_neg);
            bool valid = isPos || isNeg;
            int ridx = isPos ? posList[img][slot]
                             : (isNeg ? negList[img][slot - n_pos] : 0);

            float roi_o[4] = {0.f, 0.f, 0.f, 0.f};
            float off_o[4] = {0.f, 0.f, 0.f, 0.f};
            int lab = 0;

            if (valid) {
                unsigned short info = g_info[imgOff + ridx];
                int gidx = info >> 2;
                float4 rr = rois[img * R + ridx];
                float4 tt = gts_raw[img * G + gidx];
                const float s = 0.0009765625f;
                tt.x *= s; tt.y *= s; tt.z *= s; tt.w *= s;

                roi_o[0] = rr.x; roi_o[1] = rr.y; roi_o[2] = rr.z; roi_o[3] = rr.w;

                float rh  = fmaxf(rr.z - rr.x, 1e-7f);
                float rw2 = fmaxf(rr.w - rr.y, 1e-7f);
                float rcy = rr.x + 0.5f * rh;
                float rcx = rr.y + 0.5f * rw2;
                float gh  = fmaxf(tt.z - tt.x, 1e-7f);
                float gw  = fmaxf(tt.w - tt.y, 1e-7f);
                float gcy = tt.x + 0.5f * gh;
                float gcx = tt.y + 0.5f * gw;

                off_o[0] = ((gcy - rcy) / rh) / 0.1f;
                off_o[1] = ((gcx - rcx) / rw2) / 0.1f;
                off_o[2] = logf(gh / rh) / 0.2f;
                off_o[3] = logf(gw / rw2) / 0.2f;

                if (isPos) lab = labels[img * G + gidx];
            }

            int slotBase = (img * 64 + slot) * 4;
            float* outOff = out + (size_t)B * 64 * 4;
            float* outLab = out + (size_t)2 * B * 64 * 4;
            #pragma unroll
            for (int k = 0; k < 4; k++) {
                out[slotBase + k]    = roi_o[k];
                outOff[slotBase + k] = off_o[k];
            }
            outLab[img * 64 + slot] = (float)lab;
        }
    }
}

extern "C" void kernel_launch(void* const* d_in, const int* in_sizes, int n_in,
                              void* d_out, int out_size) {
    const float4* rois   = (const float4*)d_in[0];   // (B,R,4) f32
    const float4* gts    = (const float4*)d_in[1];   // (B,G,4) f32 raw pixels
    const int*    labels = (const int*)d_in[2];      // (B,G) i32
    float* out = (float*)d_out;

    const int G = 256;
    int B = in_sizes[2] / G;
    int R = in_sizes[0] / (4 * B);
    int nChunks = (R + CHUNK - 1) / CHUNK;

    dim3 grid(nChunks, B);
    fused_kernel<<<grid, 256>>>(rois, gts, labels, out, R, G, B, nChunks,
                                nChunks * B);
}